// round 8
// baseline (speedup 1.0000x reference)
#include <cuda_runtime.h>
#include <cuda_bf16.h>
#include <cstdint>
#include <math.h>

#define BB 128
#define TT 512
#define VV 128
#define EE 256
#define HH 1024
#define FH 4096   // 4*H

// ======================= static device scratch =======================
__device__ float g_embW[VV * FH];                    // emb@W + b, layout [v][bx*32 + jp*4 + gate]
__device__ float g_states[(size_t)BB * TT * HH];     // all h_t (256 MB)
__device__ __nv_bfloat16 g_hbf[2][2][BB * HH];       // [parity][hi/lo] split h
__device__ __nv_bfloat16 g_Ubhi[(size_t)FH * HH];    // U as [n=4j+g][k], hi part
__device__ __nv_bfloat16 g_Ublo[(size_t)FH * HH];    // lo part
__device__ unsigned g_chunk_cnt[32];                 // producer flags: 4 CTAs per chunk group
__device__ int g_tokT[TT * BB];                      // tokens transposed [t][m]

// ======================= PTX helpers (sm_100 baseline features only) =======================
__device__ __forceinline__ uint32_t smem_u32(const void* p) {
    uint32_t a;
    asm("{ .reg .u64 t; cvta.to.shared.u64 t, %1; cvt.u32.u64 %0, t; }" : "=r"(a) : "l"(p));
    return a;
}
__device__ __forceinline__ void cp16(uint32_t s, const void* g) {
    asm volatile("cp.async.cg.shared.global [%0], [%1], 16;" :: "r"(s), "l"(g));
}
#define CP_COMMIT() asm volatile("cp.async.commit_group;" ::: "memory")
#define CP_WAIT0()  asm volatile("cp.async.wait_group 0;" ::: "memory")

#define MBARRIER_INIT(mbar, cnt) \
    asm volatile("mbarrier.init.shared.b64 [%0], %1;" :: "r"((uint32_t)(mbar)), "r"((uint32_t)(cnt)) : "memory")
#define MBARRIER_ARRIVE(mbar) \
    asm volatile("mbarrier.arrive.shared.b64 _, [%0];" :: "r"((uint32_t)(mbar)) : "memory")
#define CPASYNC_MBAR_ARRIVE(mbar) \
    asm volatile("cp.async.mbarrier.arrive.noinc.shared::cta.b64 [%0];" :: "r"((uint32_t)(mbar)) : "memory")
#define MBAR_WAIT(mbar_addr, phase_parity) do { \
    uint32_t _mbar = (uint32_t)(mbar_addr); \
    uint32_t _parity = (uint32_t)(phase_parity); \
    uint32_t _done; \
    asm volatile("{\n\t.reg .pred p;\n\t" \
        "mbarrier.try_wait.parity.acquire.cta.shared::cta.b64 p, [%1], %2;\n\t" \
        "selp.b32 %0, 1, 0, p;\n\t}" : "=r"(_done) : "r"(_mbar), "r"(_parity) : "memory"); \
    if (!_done) { \
        asm volatile("{\n\t.reg .pred P1;\n\t" \
            "WAIT_LOOP_%=:\n\t" \
            "mbarrier.try_wait.parity.acquire.cta.shared::cta.b64 P1, [%0], %1, 0x989680;\n\t" \
            "@P1 bra.uni WAIT_DONE_%=;\n\t" \
            "bra.uni WAIT_LOOP_%=;\n\t" \
            "WAIT_DONE_%=:\n\t}" :: "r"(_mbar), "r"(_parity) : "memory"); \
    } \
} while (0)

__device__ __forceinline__ void ldmx4(uint32_t* r, uint32_t addr) {
    asm volatile("ldmatrix.sync.aligned.m8n8.x4.shared.b16 {%0,%1,%2,%3}, [%4];"
        : "=r"(r[0]), "=r"(r[1]), "=r"(r[2]), "=r"(r[3]) : "r"(addr));
}
__device__ __forceinline__ void mma_bf16(float* c, const uint32_t* a, const uint32_t* b) {
    asm volatile(
        "mma.sync.aligned.m16n8k16.row.col.f32.bf16.bf16.f32 "
        "{%0,%1,%2,%3}, {%4,%5,%6,%7}, {%8,%9}, {%0,%1,%2,%3};"
        : "+f"(c[0]), "+f"(c[1]), "+f"(c[2]), "+f"(c[3])
        : "r"(a[0]), "r"(a[1]), "r"(a[2]), "r"(a[3]), "r"(b[0]), "r"(b[1]));
}
// spin until *p >= need (monotonic counter in L2)
__device__ __forceinline__ void wait_cnt(const unsigned* p, unsigned need) {
    unsigned v;
    while (true) {
        asm volatile("ld.global.cg.u32 %0, [%1];" : "=r"(v) : "l"(p) : "memory");
        if (v >= need) break;
        __nanosleep(32);
    }
}
__device__ __forceinline__ float sigm_fast(float x) {
    return __fdividef(1.0f, 1.0f + __expf(-x));
}
__device__ __forceinline__ float tanh_fast(float x) {
    float xc = fminf(15.0f, fmaxf(-15.0f, x));
    float e2 = __expf(2.0f * xc);
    return __fdividef(e2 - 1.0f, e2 + 1.0f);
}

// ======================= init =======================
__global__ void zero_hc_kernel() {
    int i = blockIdx.x * blockDim.x + threadIdx.x;   // 131072 total
    if (i < 32) g_chunk_cnt[i] = 0u;                 // reset flags EVERY launch
    g_hbf[0][0][i] = __float2bfloat16(0.0f);
    g_hbf[0][1][i] = __float2bfloat16(0.0f);
}

// tokens [m][t] -> g_tokT [t][m]
__global__ void tokT_kernel(const int* __restrict__ tokens) {
    int t = blockIdx.x, m = threadIdx.x;
    g_tokT[t * BB + m] = tokens[m * TT + t];
}

// U[k][g*H + j]  ->  Ub[n = 4j+g][k], split hi/lo bf16
__global__ void usplit_kernel(const float* __restrict__ U) {
    int idx = blockIdx.x * 256 + threadIdx.x;        // 4M total
    int R = idx >> 10, k = idx & 1023;
    int j = R >> 2, g = R & 3;
    float v = U[(size_t)k * FH + g * HH + j];
    __nv_bfloat16 hi = __float2bfloat16(v);
    g_Ubhi[idx] = hi;
    g_Ublo[idx] = __float2bfloat16(v - __bfloat162float(hi));
}

// embW = emb @ W + b, stored as [v][ (j>>3)*32 + (j&7)*4 + gate ]
__global__ void embw_kernel(const float* __restrict__ emb,
                            const float* __restrict__ W,
                            const float* __restrict__ b) {
    __shared__ float se[EE];
    int v   = blockIdx.y;
    int col = blockIdx.x * blockDim.x + threadIdx.x;   // original col = g*HH + j
    se[threadIdx.x] = emb[v * EE + threadIdx.x];
    __syncthreads();
    float acc = b[col];
#pragma unroll 8
    for (int k = 0; k < EE; k++)
        acc = fmaf(se[k], W[k * FH + col], acc);
    int g = col >> 10, j = col & 1023;
    g_embW[v * FH + ((j >> 3) << 5) + ((j & 7) << 2) + g] = acc;
}

// ======================= persistent warp-specialized LSTM scan =======================
// 128 CTAs (1/SM), 640 threads: warps 0-15 compute (M16xN16 tiles), warps 16-19 load.
// CTA bx owns n = bx*32..+31 (j = bx*8..+7). U slice resident in smem.
// A ring: 4 slots of k=32 chunks, full/empty mbarriers; flags gate producers' h.
// ROTATION: CTA bx consumes chunks in order c = (bx>>2 + ii) & 31 -> wavefront pipeline.
#define UROWB   2064                       // 1024 bf16 = 2048 B + 16 pad
#define USIZE   (32 * UROWB)               // 66048 per hi/lo copy
#define OFFU    0                          // U: 132096 B
#define AROWB   80                         // 32 bf16 = 64 B + 16 pad
#define ASTAGE  (2 * 128 * AROWB)          // hi+lo per slot = 20480 B
#define OFFA    (2 * USIZE)                // A ring: 4 slots = 81920 B
#define OFFH    (OFFA + 4 * ASTAGE)        // h slice: 128*8 fp32 = 4096 B
#define OFFC    (OFFH + 4096)              // c slice: 4096 B
#define OFFM    (OFFC + 4096)              // mbarriers: 4 x (full,empty) = 64 B
#define STEP_SMEM (OFFM + 64)              // 222272 B

__global__ void __launch_bounds__(640) lstm_persistent() {
    extern __shared__ char smem[];
    const uint32_t sb  = smem_u32(smem);
    const int tid  = threadIdx.x;
    const int wid  = tid >> 5;
    const int lane = tid & 31;
    const int bx   = blockIdx.x;
    const int c0   = bx >> 2;              // rotation origin: own chunk group

    const uint32_t mb = sb + OFFM;
    // full[s] = mb + s*16; empty[s] = mb + s*16 + 8

    if (tid == 0) {
#pragma unroll
        for (int s = 0; s < 4; s++) {
            MBARRIER_INIT(mb + s * 16,     128);   // full: 128 loader threads
            MBARRIER_INIT(mb + s * 16 + 8, 512);   // empty: 512 compute threads
        }
    }

    float* s_h = (float*)(smem + OFFH);
    float* s_c = (float*)(smem + OFFC);
    for (int i = tid; i < 1024; i += 640) { s_h[i] = 0.0f; s_c[i] = 0.0f; }

    // ---- load U slice (32 n-rows x 1024 k, hi+lo) into smem once, all 640 threads ----
    for (int i = tid; i < 8192; i += 640) {   // 8192 segs of 16 B
        int sel = i >> 12, rs = i & 4095;
        int row = rs >> 7, seg = rs & 127;
        uint32_t dst = sb + OFFU + (uint32_t)sel * USIZE + (uint32_t)row * UROWB + seg * 16;
        const __nv_bfloat16* src = (sel ? g_Ublo : g_Ubhi) + (size_t)(bx * 32 + row) * HH + seg * 8;
        cp16(dst, src);
    }
    CP_COMMIT();
    CP_WAIT0();
    __syncthreads();          // last full-CTA barrier; warps specialize below

    if (wid >= 16) {
        // ================= loader warps (128 threads) =================
        const int ltid = tid - 512;
        for (int gi = 0; gi < TT * 32; gi++) {
            const int t = gi >> 5, ii = gi & 31, s = gi & 3;
            const int c = (c0 + ii) & 31;                     // rotated chunk id
            if (lane == 0) wait_cnt(&g_chunk_cnt[c], 4u * (unsigned)t);
            __syncwarp();
            MBAR_WAIT(mb + s * 16 + 8, ((gi >> 2) & 1) ^ 1);  // empty[s]
            const __nv_bfloat16* __restrict__ Ahi = g_hbf[t & 1][0];
            const __nv_bfloat16* __restrict__ Alo = g_hbf[t & 1][1];
            const int k0 = c * 32;
            const uint32_t base = sb + OFFA + (uint32_t)s * ASTAGE;
#pragma unroll
            for (int it = 0; it < 8; it++) {
                int i = ltid + it * 128;
                int sel = i >> 9, rs = i & 511;
                int row = rs >> 2, seg = rs & 3;
                cp16(base + (uint32_t)sel * (128 * AROWB) + (uint32_t)row * AROWB + seg * 16,
                     (sel ? Alo : Ahi) + row * HH + k0 + seg * 8);
            }
            CPASYNC_MBAR_ARRIVE(mb + s * 16);                 // full[s] on completion
        }
    } else {
        // ================= compute warps (512 threads) =================
        const int m0w = (wid >> 1) * 16;
        const int n0w = (wid & 1) * 16;

        for (int t = 0; t < TT; t++) {
            const int par = t & 1;

            float acc[2][4];
#pragma unroll
            for (int nq = 0; nq < 2; nq++)
#pragma unroll
                for (int r = 0; r < 4; r++) acc[nq][r] = 0.0f;

            for (int ii = 0; ii < 32; ii++) {
                const int g = t * 32 + ii, s = g & 3;
                const int c = (c0 + ii) & 31;                 // rotated chunk id
                MBAR_WAIT(mb + s * 16, (g >> 2) & 1);         // full[s]
                const uint32_t baseA = sb + OFFA + (uint32_t)s * ASTAGE;
#pragma unroll
                for (int kt = 0; kt < 2; kt++) {
                    uint32_t ah[4], al[4], bh[4], bl[4];
                    uint32_t ad = baseA + (uint32_t)(m0w + (lane & 15)) * AROWB
                                        + (uint32_t)(kt * 16 + (lane >> 4) * 8) * 2;
                    ldmx4(ah, ad);
                    ldmx4(al, ad + 128 * AROWB);
                    uint32_t bd = sb + OFFU
                                + (uint32_t)(n0w + (lane >> 4) * 8 + (lane & 7)) * UROWB
                                + (uint32_t)(c * 32 + kt * 16 + ((lane >> 3) & 1) * 8) * 2;
                    ldmx4(bh, bd);
                    ldmx4(bl, bd + USIZE);
#pragma unroll
                    for (int nq = 0; nq < 2; nq++) {
                        mma_bf16(acc[nq], ah, bh + nq * 2);   // hi*hi
                        mma_bf16(acc[nq], ah, bl + nq * 2);   // hi*lo
                        mma_bf16(acc[nq], al, bh + nq * 2);   // lo*hi
                    }
                }
                if (ii < 31) MBARRIER_ARRIVE(mb + s * 16 + 8); // empty[s]; slot 3 deferred
            }

            asm volatile("bar.sync 1, 512;" ::: "memory");    // all MMA reads done

            // ---- stage z into ring slot 3 (16896 B <= 20480 B) ----
            float* z = (float*)(smem + OFFA + 3 * ASTAGE);
#pragma unroll
            for (int nq = 0; nq < 2; nq++) {
                int r0 = m0w + (lane >> 2);
                int c0z = n0w + nq * 8 + (lane & 3) * 2;
                z[r0 * 33 + c0z]           = acc[nq][0];
                z[r0 * 33 + c0z + 1]       = acc[nq][1];
                z[(r0 + 8) * 33 + c0z]     = acc[nq][2];
                z[(r0 + 8) * 33 + c0z + 1] = acc[nq][3];
            }
            asm volatile("bar.sync 1, 512;" ::: "memory");

            // ---- fused gate epilogue (j-minor, coalesced float4 bias gather) ----
            const int jp = tid & 7;
            const int j  = bx * 8 + jp;
            __nv_bfloat16* __restrict__ hbh = g_hbf[par ^ 1][0];
            __nv_bfloat16* __restrict__ hbl = g_hbf[par ^ 1][1];

#pragma unroll
            for (int mi = 0; mi < 2; mi++) {
                int m   = (tid >> 3) + mi * 64;
                int tok = g_tokT[t * BB + m];
                bool mk = (tok != 0);
                float4 ew4 = *(const float4*)(g_embW + (size_t)tok * FH + bx * 32 + jp * 4);
                float zi = z[m * 33 + 4 * jp + 0] + ew4.x;
                float zf = z[m * 33 + 4 * jp + 1] + ew4.y;
                float zg = z[m * 33 + 4 * jp + 2] + ew4.z;
                float zo = z[m * 33 + 4 * jp + 3] + ew4.w;
                float ig = sigm_fast(zi);
                float fg = sigm_fast(zf);
                float gg = tanh_fast(zg);
                float og = sigm_fast(zo);
                float cp = s_c[m * 8 + jp];
                float cn = fg * cp + ig * gg;
                float hn = og * tanh_fast(cn);
                float hp = s_h[m * 8 + jp];
                float ho = mk ? hn : hp;
                float co = mk ? cn : cp;
                s_c[m * 8 + jp] = co;
                s_h[m * 8 + jp] = ho;
                __nv_bfloat16 hh = __float2bfloat16(ho);
                hbh[m * HH + j] = hh;
                hbl[m * HH + j] = __float2bfloat16(ho - __bfloat162float(hh));
                g_states[((size_t)m * TT + t) * HH + j] = ho;
            }

            asm volatile("bar.sync 1, 512;" ::: "memory");    // epilogue stores done
            if (tid == 0) {
                __threadfence();                              // publish h before flagging
                atomicAdd(&g_chunk_cnt[bx >> 2], 1u);
            }
            MBARRIER_ARRIVE(mb + 3 * 16 + 8);                 // release slot 3 (z region)
        }
    }
}

// ======================= logits = states @ Wd + bd =======================
__global__ void __launch_bounds__(256) logits_kernel(const float* __restrict__ Wd,
                                                     const float* __restrict__ bd,
                                                     float* __restrict__ out) {
    __shared__ float Ss[32][33];
    __shared__ float Ws[32][128];

    const int tid = threadIdx.x;
    const int tx  = tid & 31;
    const int ty  = tid >> 5;
    const size_t row0 = (size_t)blockIdx.x * 32;

    float acc[4][4];
#pragma unroll
    for (int i = 0; i < 4; i++)
#pragma unroll
        for (int jn = 0; jn < 4; jn++) acc[i][jn] = 0.0f;

    for (int k0 = 0; k0 < HH; k0 += 32) {
#pragma unroll
        for (int r = 0; r < 4; r++) {
            int idx = tid + r * 256;
            int rr = idx >> 5, kk = idx & 31;
            Ss[rr][kk] = g_states[(row0 + rr) * HH + k0 + kk];
        }
#pragma unroll
        for (int r = 0; r < 16; r++) {
            int idx = tid + r * 256;
            int kk = idx >> 7, v = idx & 127;
            Ws[kk][v] = Wd[(k0 + kk) * VV + v];
        }
        __syncthreads();
#pragma unroll
        for (int kk = 0; kk < 32; kk++) {
            float4 b4 = *reinterpret_cast<const float4*>(&Ws[kk][tx * 4]);
            float a0 = Ss[ty * 4 + 0][kk];
            float a1 = Ss[ty * 4 + 1][kk];
            float a2 = Ss[ty * 4 + 2][kk];
            float a3 = Ss[ty * 4 + 3][kk];
            acc[0][0] = fmaf(a0, b4.x, acc[0][0]);
            acc[0][1] = fmaf(a0, b4.y, acc[0][1]);
            acc[0][2] = fmaf(a0, b4.z, acc[0][2]);
            acc[0][3] = fmaf(a0, b4.w, acc[0][3]);
            acc[1][0] = fmaf(a1, b4.x, acc[1][0]);
            acc[1][1] = fmaf(a1, b4.y, acc[1][1]);
            acc[1][2] = fmaf(a1, b4.z, acc[1][2]);
            acc[1][3] = fmaf(a1, b4.w, acc[1][3]);
            acc[2][0] = fmaf(a2, b4.x, acc[2][0]);
            acc[2][1] = fmaf(a2, b4.y, acc[2][1]);
            acc[2][2] = fmaf(a2, b4.z, acc[2][2]);
            acc[2][3] = fmaf(a2, b4.w, acc[2][3]);
            acc[3][0] = fmaf(a3, b4.x, acc[3][0]);
            acc[3][1] = fmaf(a3, b4.y, acc[3][1]);
            acc[3][2] = fmaf(a3, b4.z, acc[3][2]);
            acc[3][3] = fmaf(a3, b4.w, acc[3][3]);
        }
        __syncthreads();
    }

#pragma unroll
    for (int im = 0; im < 4; im++)
#pragma unroll
        for (int iv = 0; iv < 4; iv++) {
            int v = tx * 4 + iv;
            out[(row0 + ty * 4 + im) * VV + v] = acc[im][iv] + bd[v];
        }
}

// ======================= row softmax (V=128) =======================
__global__ void softmax_kernel(float* __restrict__ out) {
    __shared__ float red[4];
    const size_t row = blockIdx.x;
    const int v    = threadIdx.x;
    const int lane = v & 31;
    const int wid  = v >> 5;

    float x = out[row * VV + v];

    float mval = x;
#pragma unroll
    for (int o = 16; o > 0; o >>= 1)
        mval = fmaxf(mval, __shfl_xor_sync(0xFFFFFFFFu, mval, o));
    if (lane == 0) red[wid] = mval;
    __syncthreads();
    mval = fmaxf(fmaxf(red[0], red[1]), fmaxf(red[2], red[3]));
    __syncthreads();

    float e = expf(x - mval);
    float s = e;
#pragma unroll
    for (int o = 16; o > 0; o >>= 1)
        s += __shfl_xor_sync(0xFFFFFFFFu, s, o);
    if (lane == 0) red[wid] = s;
    __syncthreads();
    s = red[0] + red[1] + red[2] + red[3];

    out[row * VV + v] = e / s;
}

// ======================= launch =======================
extern "C" void kernel_launch(void* const* d_in, const int* in_sizes, int n_in,
                              void* d_out, int out_size) {
    const int*   tokens = (const int*)  d_in[0];
    const float* emb    = (const float*)d_in[1];
    const float* W      = (const float*)d_in[2];
    const float* U      = (const float*)d_in[3];
    const float* b      = (const float*)d_in[4];
    const float* Wd     = (const float*)d_in[5];
    const float* bd     = (const float*)d_in[6];
    float* out = (float*)d_out;

    cudaFuncSetAttribute(lstm_persistent, cudaFuncAttributeMaxDynamicSharedMemorySize, STEP_SMEM);

    zero_hc_kernel<<<512, 256>>>();
    tokT_kernel<<<TT, BB>>>(tokens);
    usplit_kernel<<<(FH * HH) / 256, 256>>>(U);
    embw_kernel<<<dim3(16, 128), 256>>>(emb, W, b);

    lstm_persistent<<<128, 640, STEP_SMEM>>>();

    logits_kernel<<<2048, 256>>>(Wd, bd, out);
    softmax_kernel<<<BB * TT, 128>>>(out);
}

// round 10
// speedup vs baseline: 1.9623x; 1.9623x over previous
#include <cuda_runtime.h>
#include <cuda_bf16.h>
#include <cuda_fp16.h>
#include <cstdint>
#include <math.h>

#define BB 128
#define TT 512
#define VV 128
#define EE 256
#define HH 1024
#define FH 4096   // 4*H

// ======================= static device scratch =======================
__device__ float g_embW[VV * FH];                    // emb@W + b, layout [v][(j>>3)*32 + (j&7)*4 + g]
__device__ float g_states[(size_t)BB * TT * HH];     // all h_t (256 MB)
__device__ __half g_hf16[2][BB * HH];                // [parity] h rounded to fp16 (single)
__device__ __half g_Uhi[(size_t)FH * HH];            // U as [n=4j+g][k], fp16 hi
__device__ __half g_Ulo[(size_t)FH * HH];            // fp16 lo (residual; may be subnormal)
__device__ unsigned g_chunk_cnt[16];                 // producer flags: 8 CTAs per k64-chunk group
__device__ int g_tokT[TT * BB];                      // tokens transposed [t][m]

// ======================= PTX helpers (sm_100 baseline features only) =======================
__device__ __forceinline__ uint32_t smem_u32(const void* p) {
    uint32_t a;
    asm("{ .reg .u64 t; cvta.to.shared.u64 t, %1; cvt.u32.u64 %0, t; }" : "=r"(a) : "l"(p));
    return a;
}
__device__ __forceinline__ void cp16(uint32_t s, const void* g) {
    asm volatile("cp.async.cg.shared.global [%0], [%1], 16;" :: "r"(s), "l"(g));
}
#define CP_COMMIT() asm volatile("cp.async.commit_group;" ::: "memory")
#define CP_WAIT0()  asm volatile("cp.async.wait_group 0;" ::: "memory")

#define MBARRIER_INIT(mbar, cnt) \
    asm volatile("mbarrier.init.shared.b64 [%0], %1;" :: "r"((uint32_t)(mbar)), "r"((uint32_t)(cnt)) : "memory")
#define MBARRIER_ARRIVE(mbar) \
    asm volatile("mbarrier.arrive.shared.b64 _, [%0];" :: "r"((uint32_t)(mbar)) : "memory")
#define CPASYNC_MBAR_ARRIVE(mbar) \
    asm volatile("cp.async.mbarrier.arrive.noinc.shared::cta.b64 [%0];" :: "r"((uint32_t)(mbar)) : "memory")
#define MBAR_WAIT(mbar_addr, phase_parity) do { \
    uint32_t _mbar = (uint32_t)(mbar_addr); \
    uint32_t _parity = (uint32_t)(phase_parity); \
    uint32_t _done; \
    asm volatile("{\n\t.reg .pred p;\n\t" \
        "mbarrier.try_wait.parity.acquire.cta.shared::cta.b64 p, [%1], %2;\n\t" \
        "selp.b32 %0, 1, 0, p;\n\t}" : "=r"(_done) : "r"(_mbar), "r"(_parity) : "memory"); \
    if (!_done) { \
        asm volatile("{\n\t.reg .pred P1;\n\t" \
            "WAIT_LOOP_%=:\n\t" \
            "mbarrier.try_wait.parity.acquire.cta.shared::cta.b64 P1, [%0], %1, 0x989680;\n\t" \
            "@P1 bra.uni WAIT_DONE_%=;\n\t" \
            "bra.uni WAIT_LOOP_%=;\n\t" \
            "WAIT_DONE_%=:\n\t}" :: "r"(_mbar), "r"(_parity) : "memory"); \
    } \
} while (0)

__device__ __forceinline__ void ldmx4(uint32_t* r, uint32_t addr) {
    asm volatile("ldmatrix.sync.aligned.m8n8.x4.shared.b16 {%0,%1,%2,%3}, [%4];"
        : "=r"(r[0]), "=r"(r[1]), "=r"(r[2]), "=r"(r[3]) : "r"(addr));
}
__device__ __forceinline__ void mma_f16(float* c, const uint32_t* a, const uint32_t* b) {
    asm volatile(
        "mma.sync.aligned.m16n8k16.row.col.f32.f16.f16.f32 "
        "{%0,%1,%2,%3}, {%4,%5,%6,%7}, {%8,%9}, {%0,%1,%2,%3};"
        : "+f"(c[0]), "+f"(c[1]), "+f"(c[2]), "+f"(c[3])
        : "r"(a[0]), "r"(a[1]), "r"(a[2]), "r"(a[3]), "r"(b[0]), "r"(b[1]));
}
// spin until *p >= need (monotonic counter in L2)
__device__ __forceinline__ void wait_cnt(const unsigned* p, unsigned need) {
    unsigned v;
    while (true) {
        asm volatile("ld.global.cg.u32 %0, [%1];" : "=r"(v) : "l"(p) : "memory");
        if (v >= need) break;
        __nanosleep(32);
    }
}
__device__ __forceinline__ float sigm_fast(float x) {
    return __fdividef(1.0f, 1.0f + __expf(-x));
}
__device__ __forceinline__ float tanh_fast(float x) {
    float xc = fminf(15.0f, fmaxf(-15.0f, x));
    float e2 = __expf(2.0f * xc);
    return __fdividef(e2 - 1.0f, e2 + 1.0f);
}

// ======================= init =======================
__global__ void zero_hc_kernel() {
    int i = blockIdx.x * blockDim.x + threadIdx.x;   // 131072 total
    if (i < 16) g_chunk_cnt[i] = 0u;                 // reset flags EVERY launch
    g_hf16[0][i] = __float2half(0.0f);
}

// tokens [m][t] -> g_tokT [t][m]
__global__ void tokT_kernel(const int* __restrict__ tokens) {
    int t = blockIdx.x, m = threadIdx.x;
    g_tokT[t * BB + m] = tokens[m * TT + t];
}

// U[k][g*H + j]  ->  U[n = 4j+g][k], split exact fp16 hi + fp16 lo
__global__ void usplit_kernel(const float* __restrict__ U) {
    int idx = blockIdx.x * 256 + threadIdx.x;        // 4M total
    int R = idx >> 10, k = idx & 1023;
    int j = R >> 2, g = R & 3;
    float v = U[(size_t)k * FH + g * HH + j];
    __half hi = __float2half(v);
    g_Uhi[idx] = hi;
    g_Ulo[idx] = __float2half(v - __half2float(hi));
}

// embW = emb @ W + b, stored as [v][ (j>>3)*32 + (j&7)*4 + gate ]
__global__ void embw_kernel(const float* __restrict__ emb,
                            const float* __restrict__ W,
                            const float* __restrict__ b) {
    __shared__ float se[EE];
    int v   = blockIdx.y;
    int col = blockIdx.x * blockDim.x + threadIdx.x;   // original col = g*HH + j
    se[threadIdx.x] = emb[v * EE + threadIdx.x];
    __syncthreads();
    float acc = b[col];
#pragma unroll 8
    for (int k = 0; k < EE; k++)
        acc = fmaf(se[k], W[k * FH + col], acc);
    int g = col >> 10, j = col & 1023;
    g_embW[v * FH + ((j >> 3) << 5) + ((j & 7) << 2) + g] = acc;
}

// ======================= persistent warp-specialized LSTM scan =======================
// 128 CTAs (1/SM), 640 threads: warps 0-15 compute (M16xN16 tiles), warps 16-19 load.
// CTA bx owns n = bx*32..+31 (j = bx*8..+7). U (fp16 hi+lo) resident in smem.
// A = h(fp16, single) streamed in 16 chunks of k=64 via 4-slot cp.async ring.
// 2-pass mma: A*Uhi + A*Ulo (error = fp16 truncation of h only, ~2^-12).
#define UROWB   2064                       // 1024 fp16 = 2048 B + 16 pad
#define USIZE   (32 * UROWB)               // 66048 per hi/lo copy
#define OFFU    0                          // U: 132096 B
#define AROWB   144                        // 64 fp16 = 128 B + 16 pad
#define ASLOT   (128 * AROWB)              // 18432 B per slot
#define OFFA    (2 * USIZE)                // A ring: 4 slots = 73728 B
#define OFFH    (OFFA + 4 * ASLOT)         // h slice: 128*8 fp32 = 4096 B
#define OFFC    (OFFH + 4096)              // c slice: 4096 B
#define OFFM    (OFFC + 4096)              // mbarriers: 4 x (full,empty) = 64 B
#define STEP_SMEM (OFFM + 64)              // 214080 B

__global__ void __launch_bounds__(640) lstm_persistent() {
    extern __shared__ char smem[];
    const uint32_t sb  = smem_u32(smem);
    const int tid  = threadIdx.x;
    const int wid  = tid >> 5;
    const int lane = tid & 31;
    const int bx   = blockIdx.x;
    const int c0   = bx >> 3;              // rotation origin: own chunk group (k64)

    const uint32_t mb = sb + OFFM;
    // full[s] = mb + s*16; empty[s] = mb + s*16 + 8

    if (tid == 0) {
#pragma unroll
        for (int s = 0; s < 4; s++) {
            MBARRIER_INIT(mb + s * 16,     128);   // full: 128 loader threads
            MBARRIER_INIT(mb + s * 16 + 8, 512);   // empty: 512 compute threads
        }
    }

    float* s_h = (float*)(smem + OFFH);
    float* s_c = (float*)(smem + OFFC);
    for (int i = tid; i < 1024; i += 640) { s_h[i] = 0.0f; s_c[i] = 0.0f; }

    // ---- load U slice (32 n-rows x 1024 k, fp16 hi+lo) into smem once ----
    for (int i = tid; i < 8192; i += 640) {   // 8192 segs of 16 B
        int sel = i >> 12, rs = i & 4095;
        int row = rs >> 7, seg = rs & 127;
        uint32_t dst = sb + OFFU + (uint32_t)sel * USIZE + (uint32_t)row * UROWB + seg * 16;
        const __half* src = (sel ? g_Ulo : g_Uhi) + (size_t)(bx * 32 + row) * HH + seg * 8;
        cp16(dst, src);
    }
    CP_COMMIT();
    CP_WAIT0();
    __syncthreads();          // last full-CTA barrier; warps specialize below

    if (wid >= 16) {
        // ================= loader warps (128 threads) =================
        const int ltid = tid - 512;
        for (int gi = 0; gi < TT * 16; gi++) {
            const int t = gi >> 4, ii = gi & 15, s = gi & 3;
            const int c = (c0 + ii) & 15;                     // rotated k64-chunk id
            if (lane == 0) wait_cnt(&g_chunk_cnt[c], 8u * (unsigned)t);
            __syncwarp();
            MBAR_WAIT(mb + s * 16 + 8, ((gi >> 2) & 1) ^ 1);  // empty[s]
            const __half* __restrict__ A = g_hf16[t & 1];
            const int k0 = c * 64;
            const uint32_t base = sb + OFFA + (uint32_t)s * ASLOT;
#pragma unroll
            for (int it = 0; it < 8; it++) {
                int i = ltid + it * 128;                      // 1024 segs of 16 B
                int row = i >> 3, seg = i & 7;
                cp16(base + (uint32_t)row * AROWB + seg * 16,
                     A + row * HH + k0 + seg * 8);
            }
            CPASYNC_MBAR_ARRIVE(mb + s * 16);                 // full[s] on completion
        }
    } else {
        // ================= compute warps (512 threads) =================
        const int m0w = (wid >> 1) * 16;
        const int n0w = (wid & 1) * 16;

        for (int t = 0; t < TT; t++) {
            const int par = t & 1;

            float acc[2][4];
#pragma unroll
            for (int nq = 0; nq < 2; nq++)
#pragma unroll
                for (int r = 0; r < 4; r++) acc[nq][r] = 0.0f;

            for (int ii = 0; ii < 16; ii++) {
                const int gi = t * 16 + ii, s = gi & 3;
                const int c = (c0 + ii) & 15;                 // rotated chunk id
                MBAR_WAIT(mb + s * 16, (gi >> 2) & 1);        // full[s]
                const uint32_t baseA = sb + OFFA + (uint32_t)s * ASLOT;
                const uint32_t aRow  = baseA + (uint32_t)(m0w + (lane & 15)) * AROWB
                                             + (uint32_t)((lane >> 4) * 8) * 2;
                const uint32_t bRow  = sb + OFFU
                                     + (uint32_t)(n0w + (lane >> 4) * 8 + (lane & 7)) * UROWB
                                     + (uint32_t)(c * 64 + ((lane >> 3) & 1) * 8) * 2;

                uint32_t ah[2][4], bh[2][4], bl[2][4];
                // prefetch kt=0
                ldmx4(ah[0], aRow);
                ldmx4(bh[0], bRow);
                ldmx4(bl[0], bRow + USIZE);
#pragma unroll
                for (int kt = 0; kt < 4; kt++) {
                    const int buf = kt & 1;
                    if (kt < 3) {                             // prefetch kt+1
                        ldmx4(ah[buf ^ 1], aRow + (uint32_t)((kt + 1) * 16) * 2);
                        ldmx4(bh[buf ^ 1], bRow + (uint32_t)((kt + 1) * 16) * 2);
                        ldmx4(bl[buf ^ 1], bRow + (uint32_t)((kt + 1) * 16) * 2 + USIZE);
                    } else if (ii < 15) {
                        MBARRIER_ARRIVE(mb + s * 16 + 8);     // empty[s]: frags in regs
                    }
#pragma unroll
                    for (int nq = 0; nq < 2; nq++) {
                        mma_f16(acc[nq], ah[buf], bh[buf] + nq * 2);  // A * Uhi
                        mma_f16(acc[nq], ah[buf], bl[buf] + nq * 2);  // A * Ulo
                    }
                }
            }

            asm volatile("bar.sync 1, 512;" ::: "memory");    // all MMA reads done

            // ---- stage z into ring slot 3 (16896 B <= 18432 B) ----
            float* z = (float*)(smem + OFFA + 3 * ASLOT);
#pragma unroll
            for (int nq = 0; nq < 2; nq++) {
                int r0 = m0w + (lane >> 2);
                int c0z = n0w + nq * 8 + (lane & 3) * 2;
                z[r0 * 33 + c0z]           = acc[nq][0];
                z[r0 * 33 + c0z + 1]       = acc[nq][1];
                z[(r0 + 8) * 33 + c0z]     = acc[nq][2];
                z[(r0 + 8) * 33 + c0z + 1] = acc[nq][3];
            }
            asm volatile("bar.sync 1, 512;" ::: "memory");

            // ---- fused gate epilogue (j-minor, coalesced float4 bias gather) ----
            const int jp = tid & 7;
            const int j  = bx * 8 + jp;
            __half* __restrict__ hf = g_hf16[par ^ 1];

#pragma unroll
            for (int mi = 0; mi < 2; mi++) {
                int m   = (tid >> 3) + mi * 64;
                int tok = g_tokT[t * BB + m];
                bool mk = (tok != 0);
                float4 ew4 = *(const float4*)(g_embW + (size_t)tok * FH + bx * 32 + jp * 4);
                float zi = z[m * 33 + 4 * jp + 0] + ew4.x;
                float zf = z[m * 33 + 4 * jp + 1] + ew4.y;
                float zg = z[m * 33 + 4 * jp + 2] + ew4.z;
                float zo = z[m * 33 + 4 * jp + 3] + ew4.w;
                float ig = sigm_fast(zi);
                float fg = sigm_fast(zf);
                float gg = tanh_fast(zg);
                float og = sigm_fast(zo);
                float cp = s_c[m * 8 + jp];
                float cn = fg * cp + ig * gg;
                float hn = og * tanh_fast(cn);
                float hp = s_h[m * 8 + jp];
                float ho = mk ? hn : hp;
                float co = mk ? cn : cp;
                s_c[m * 8 + jp] = co;
                s_h[m * 8 + jp] = ho;
                hf[m * HH + j] = __float2half(ho);
                g_states[((size_t)m * TT + t) * HH + j] = ho;
            }

            asm volatile("bar.sync 1, 512;" ::: "memory");    // epilogue stores done
            if (tid == 0) {
                __threadfence();                              // publish h before flagging
                atomicAdd(&g_chunk_cnt[bx >> 3], 1u);
            }
            MBARRIER_ARRIVE(mb + 3 * 16 + 8);                 // release slot 3 (z region)
        }
    }
}

// ======================= logits = states @ Wd + bd =======================
__global__ void __launch_bounds__(256) logits_kernel(const float* __restrict__ Wd,
                                                     const float* __restrict__ bd,
                                                     float* __restrict__ out) {
    __shared__ float Ss[32][33];
    __shared__ float Ws[32][128];

    const int tid = threadIdx.x;
    const int tx  = tid & 31;
    const int ty  = tid >> 5;
    const size_t row0 = (size_t)blockIdx.x * 32;

    float acc[4][4];
#pragma unroll
    for (int i = 0; i < 4; i++)
#pragma unroll
        for (int jn = 0; jn < 4; jn++) acc[i][jn] = 0.0f;

    for (int k0 = 0; k0 < HH; k0 += 32) {
#pragma unroll
        for (int r = 0; r < 4; r++) {
            int idx = tid + r * 256;
            int rr = idx >> 5, kk = idx & 31;
            Ss[rr][kk] = g_states[(row0 + rr) * HH + k0 + kk];
        }
#pragma unroll
        for (int r = 0; r < 16; r++) {
            int idx = tid + r * 256;
            int kk = idx >> 7, v = idx & 127;
            Ws[kk][v] = Wd[(k0 + kk) * VV + v];
        }
        __syncthreads();
#pragma unroll
        for (int kk = 0; kk < 32; kk++) {
            float4 b4 = *reinterpret_cast<const float4*>(&Ws[kk][tx * 4]);
            float a0 = Ss[ty * 4 + 0][kk];
            float a1 = Ss[ty * 4 + 1][kk];
            float a2 = Ss[ty * 4 + 2][kk];
            float a3 = Ss[ty * 4 + 3][kk];
            acc[0][0] = fmaf(a0, b4.x, acc[0][0]);
            acc[0][1] = fmaf(a0, b4.y, acc[0][1]);
            acc[0][2] = fmaf(a0, b4.z, acc[0][2]);
            acc[0][3] = fmaf(a0, b4.w, acc[0][3]);
            acc[1][0] = fmaf(a1, b4.x, acc[1][0]);
            acc[1][1] = fmaf(a1, b4.y, acc[1][1]);
            acc[1][2] = fmaf(a1, b4.z, acc[1][2]);
            acc[1][3] = fmaf(a1, b4.w, acc[1][3]);
            acc[2][0] = fmaf(a2, b4.x, acc[2][0]);
            acc[2][1] = fmaf(a2, b4.y, acc[2][1]);
            acc[2][2] = fmaf(a2, b4.z, acc[2][2]);
            acc[2][3] = fmaf(a2, b4.w, acc[2][3]);
            acc[3][0] = fmaf(a3, b4.x, acc[3][0]);
            acc[3][1] = fmaf(a3, b4.y, acc[3][1]);
            acc[3][2] = fmaf(a3, b4.z, acc[3][2]);
            acc[3][3] = fmaf(a3, b4.w, acc[3][3]);
        }
        __syncthreads();
    }

#pragma unroll
    for (int im = 0; im < 4; im++)
#pragma unroll
        for (int iv = 0; iv < 4; iv++) {
            int v = tx * 4 + iv;
            out[(row0 + ty * 4 + im) * VV + v] = acc[im][iv] + bd[v];
        }
}

// ======================= row softmax (V=128) =======================
__global__ void softmax_kernel(float* __restrict__ out) {
    __shared__ float red[4];
    const size_t row = blockIdx.x;
    const int v    = threadIdx.x;
    const int lane = v & 31;
    const int wid  = v >> 5;

    float x = out[row * VV + v];

    float mval = x;
#pragma unroll
    for (int o = 16; o > 0; o >>= 1)
        mval = fmaxf(mval, __shfl_xor_sync(0xFFFFFFFFu, mval, o));
    if (lane == 0) red[wid] = mval;
    __syncthreads();
    mval = fmaxf(fmaxf(red[0], red[1]), fmaxf(red[2], red[3]));
    __syncthreads();

    float e = expf(x - mval);
    float s = e;
#pragma unroll
    for (int o = 16; o > 0; o >>= 1)
        s += __shfl_xor_sync(0xFFFFFFFFu, s, o);
    if (lane == 0) red[wid] = s;
    __syncthreads();
    s = red[0] + red[1] + red[2] + red[3];

    out[row * VV + v] = e / s;
}

// ======================= launch =======================
extern "C" void kernel_launch(void* const* d_in, const int* in_sizes, int n_in,
                              void* d_out, int out_size) {
    const int*   tokens = (const int*)  d_in[0];
    const float* emb    = (const float*)d_in[1];
    const float* W      = (const float*)d_in[2];
    const float* U      = (const float*)d_in[3];
    const float* b      = (const float*)d_in[4];
    const float* Wd     = (const float*)d_in[5];
    const float* bd     = (const float*)d_in[6];
    float* out = (float*)d_out;

    cudaFuncSetAttribute(lstm_persistent, cudaFuncAttributeMaxDynamicSharedMemorySize, STEP_SMEM);

    zero_hc_kernel<<<512, 256>>>();
    tokT_kernel<<<TT, BB>>>(tokens);
    usplit_kernel<<<(FH * HH) / 256, 256>>>(U);
    embw_kernel<<<dim3(16, 128), 256>>>(emb, W, b);

    lstm_persistent<<<128, 640, STEP_SMEM>>>();

    logits_kernel<<<2048, 256>>>(Wd, bd, out);
    softmax_kernel<<<BB * TT, 128>>>(out);
}

// round 11
// speedup vs baseline: 1.9755x; 1.0067x over previous
#include <cuda_runtime.h>
#include <cuda_bf16.h>
#include <cuda_fp16.h>
#include <cstdint>
#include <math.h>

#define BB 128
#define TT 512
#define VV 128
#define EE 256
#define HH 1024
#define FH 4096   // 4*H

// ======================= static device scratch =======================
__device__ float g_embW[VV * FH];                    // emb@W + b, layout [v][(j>>3)*32 + (j&7)*4 + g]
__device__ float g_states[(size_t)BB * TT * HH];     // all h_t (256 MB)
__device__ __half g_hf16[2][BB * HH];                // [parity] h rounded to fp16 (single)
__device__ __half g_Uhi[(size_t)FH * HH];            // U as [n=4j+g][k], fp16 hi
__device__ __half g_Ulo[(size_t)FH * HH];            // fp16 lo (residual; may be subnormal)
__device__ unsigned g_chunk_cnt[16];                 // producer flags: 8 CTAs per k64-chunk group
__device__ int g_tokT[TT * BB];                      // tokens transposed [t][m]

// ======================= PTX helpers (sm_100 baseline features only) =======================
__device__ __forceinline__ uint32_t smem_u32(const void* p) {
    uint32_t a;
    asm("{ .reg .u64 t; cvta.to.shared.u64 t, %1; cvt.u32.u64 %0, t; }" : "=r"(a) : "l"(p));
    return a;
}
__device__ __forceinline__ void cp16(uint32_t s, const void* g) {
    asm volatile("cp.async.cg.shared.global [%0], [%1], 16;" :: "r"(s), "l"(g));
}
#define CP_COMMIT() asm volatile("cp.async.commit_group;" ::: "memory")
#define CP_WAIT0()  asm volatile("cp.async.wait_group 0;" ::: "memory")

#define MBARRIER_INIT(mbar, cnt) \
    asm volatile("mbarrier.init.shared.b64 [%0], %1;" :: "r"((uint32_t)(mbar)), "r"((uint32_t)(cnt)) : "memory")
#define MBARRIER_ARRIVE(mbar) \
    asm volatile("mbarrier.arrive.shared.b64 _, [%0];" :: "r"((uint32_t)(mbar)) : "memory")
#define CPASYNC_MBAR_ARRIVE(mbar) \
    asm volatile("cp.async.mbarrier.arrive.noinc.shared::cta.b64 [%0];" :: "r"((uint32_t)(mbar)) : "memory")
#define MBAR_WAIT(mbar_addr, phase_parity) do { \
    uint32_t _mbar = (uint32_t)(mbar_addr); \
    uint32_t _parity = (uint32_t)(phase_parity); \
    uint32_t _done; \
    asm volatile("{\n\t.reg .pred p;\n\t" \
        "mbarrier.try_wait.parity.acquire.cta.shared::cta.b64 p, [%1], %2;\n\t" \
        "selp.b32 %0, 1, 0, p;\n\t}" : "=r"(_done) : "r"(_mbar), "r"(_parity) : "memory"); \
    if (!_done) { \
        asm volatile("{\n\t.reg .pred P1;\n\t" \
            "WAIT_LOOP_%=:\n\t" \
            "mbarrier.try_wait.parity.acquire.cta.shared::cta.b64 P1, [%0], %1, 0x989680;\n\t" \
            "@P1 bra.uni WAIT_DONE_%=;\n\t" \
            "bra.uni WAIT_LOOP_%=;\n\t" \
            "WAIT_DONE_%=:\n\t}" :: "r"(_mbar), "r"(_parity) : "memory"); \
    } \
} while (0)

__device__ __forceinline__ void ldmx4(uint32_t* r, uint32_t addr) {
    asm volatile("ldmatrix.sync.aligned.m8n8.x4.shared.b16 {%0,%1,%2,%3}, [%4];"
        : "=r"(r[0]), "=r"(r[1]), "=r"(r[2]), "=r"(r[3]) : "r"(addr));
}
__device__ __forceinline__ void mma_f16(float* c, const uint32_t* a, const uint32_t* b) {
    asm volatile(
        "mma.sync.aligned.m16n8k16.row.col.f32.f16.f16.f32 "
        "{%0,%1,%2,%3}, {%4,%5,%6,%7}, {%8,%9}, {%0,%1,%2,%3};"
        : "+f"(c[0]), "+f"(c[1]), "+f"(c[2]), "+f"(c[3])
        : "r"(a[0]), "r"(a[1]), "r"(a[2]), "r"(a[3]), "r"(b[0]), "r"(b[1]));
}
// spin until *p >= need (monotonic counter in L2)
__device__ __forceinline__ void wait_cnt(const unsigned* p, unsigned need) {
    unsigned v;
    while (true) {
        asm volatile("ld.global.cg.u32 %0, [%1];" : "=r"(v) : "l"(p) : "memory");
        if (v >= need) break;
        __nanosleep(32);
    }
}
__device__ __forceinline__ float sigm_fast(float x) {
    return __fdividef(1.0f, 1.0f + __expf(-x));
}
__device__ __forceinline__ float tanh_fast(float x) {
    float xc = fminf(15.0f, fmaxf(-15.0f, x));
    float e2 = __expf(2.0f * xc);
    return __fdividef(e2 - 1.0f, e2 + 1.0f);
}

// ======================= init =======================
__global__ void zero_hc_kernel() {
    int i = blockIdx.x * blockDim.x + threadIdx.x;   // 131072 total
    if (i < 16) g_chunk_cnt[i] = 0u;                 // reset flags EVERY launch
    g_hf16[0][i] = __float2half(0.0f);
}

// tokens [m][t] -> g_tokT [t][m]
__global__ void tokT_kernel(const int* __restrict__ tokens) {
    int t = blockIdx.x, m = threadIdx.x;
    g_tokT[t * BB + m] = tokens[m * TT + t];
}

// U[k][g*H + j]  ->  U[n = 4j+g][k], split exact fp16 hi + fp16 lo
__global__ void usplit_kernel(const float* __restrict__ U) {
    int idx = blockIdx.x * 256 + threadIdx.x;        // 4M total
    int R = idx >> 10, k = idx & 1023;
    int j = R >> 2, g = R & 3;
    float v = U[(size_t)k * FH + g * HH + j];
    __half hi = __float2half(v);
    g_Uhi[idx] = hi;
    g_Ulo[idx] = __float2half(v - __half2float(hi));
}

// embW = emb @ W + b, stored as [v][ (j>>3)*32 + (j&7)*4 + gate ]
__global__ void embw_kernel(const float* __restrict__ emb,
                            const float* __restrict__ W,
                            const float* __restrict__ b) {
    __shared__ float se[EE];
    int v   = blockIdx.y;
    int col = blockIdx.x * blockDim.x + threadIdx.x;   // original col = g*HH + j
    se[threadIdx.x] = emb[v * EE + threadIdx.x];
    __syncthreads();
    float acc = b[col];
#pragma unroll 8
    for (int k = 0; k < EE; k++)
        acc = fmaf(se[k], W[k * FH + col], acc);
    int g = col >> 10, j = col & 1023;
    g_embW[v * FH + ((j >> 3) << 5) + ((j & 7) << 2) + g] = acc;
}

// ======================= persistent warp-specialized LSTM scan =======================
// 128 CTAs (1/SM), 640 threads: warps 0-15 compute (M16xN16 tiles), warps 16-19 load.
// CTA bx owns n = bx*32..+31 (j = bx*8..+7). U (fp16 hi+lo) resident in smem.
// A = h(fp16, single) streamed in 16 chunks of k=64 via 4-slot cp.async ring.
// 2-pass mma: A*Uhi + A*Ulo (error = fp16 truncation of h only, ~2^-12).
#define UROWB   2064                       // 1024 fp16 = 2048 B + 16 pad
#define USIZE   (32 * UROWB)               // 66048 per hi/lo copy
#define OFFU    0                          // U: 132096 B
#define AROWB   144                        // 64 fp16 = 128 B + 16 pad
#define ASLOT   (128 * AROWB)              // 18432 B per slot
#define OFFA    (2 * USIZE)                // A ring: 4 slots = 73728 B
#define OFFH    (OFFA + 4 * ASLOT)         // h slice: 128*8 fp32 = 4096 B
#define OFFC    (OFFH + 4096)              // c slice: 4096 B
#define OFFM    (OFFC + 4096)              // mbarriers: 4 x (full,empty) = 64 B
#define STEP_SMEM (OFFM + 64)              // 214080 B

__global__ void __launch_bounds__(640) lstm_persistent() {
    extern __shared__ char smem[];
    const uint32_t sb  = smem_u32(smem);
    const int tid  = threadIdx.x;
    const int wid  = tid >> 5;
    const int lane = tid & 31;
    const int bx   = blockIdx.x;
    const int c0   = bx >> 3;              // rotation origin: own chunk group (k64)

    const uint32_t mb = sb + OFFM;
    // full[s] = mb + s*16; empty[s] = mb + s*16 + 8

    if (tid == 0) {
#pragma unroll
        for (int s = 0; s < 4; s++) {
            MBARRIER_INIT(mb + s * 16,     128);   // full: 128 loader threads
            MBARRIER_INIT(mb + s * 16 + 8, 512);   // empty: 512 compute threads
        }
    }

    float* s_h = (float*)(smem + OFFH);
    float* s_c = (float*)(smem + OFFC);
    for (int i = tid; i < 1024; i += 640) { s_h[i] = 0.0f; s_c[i] = 0.0f; }

    // ---- load U slice (32 n-rows x 1024 k, fp16 hi+lo) into smem once ----
    for (int i = tid; i < 8192; i += 640) {   // 8192 segs of 16 B
        int sel = i >> 12, rs = i & 4095;
        int row = rs >> 7, seg = rs & 127;
        uint32_t dst = sb + OFFU + (uint32_t)sel * USIZE + (uint32_t)row * UROWB + seg * 16;
        const __half* src = (sel ? g_Ulo : g_Uhi) + (size_t)(bx * 32 + row) * HH + seg * 8;
        cp16(dst, src);
    }
    CP_COMMIT();
    CP_WAIT0();
    __syncthreads();          // last full-CTA barrier; warps specialize below

    if (wid >= 16) {
        // ================= loader warps (128 threads) =================
        const int ltid = tid - 512;
        for (int gi = 0; gi < TT * 16; gi++) {
            const int t = gi >> 4, ii = gi & 15, s = gi & 3;
            const int c = (c0 + ii) & 15;                     // rotated k64-chunk id
            if (lane == 0) wait_cnt(&g_chunk_cnt[c], 8u * (unsigned)t);
            __syncwarp();
            MBAR_WAIT(mb + s * 16 + 8, ((gi >> 2) & 1) ^ 1);  // empty[s]
            const __half* __restrict__ A = g_hf16[t & 1];
            const int k0 = c * 64;
            const uint32_t base = sb + OFFA + (uint32_t)s * ASLOT;
#pragma unroll
            for (int it = 0; it < 8; it++) {
                int i = ltid + it * 128;                      // 1024 segs of 16 B
                int row = i >> 3, seg = i & 7;
                cp16(base + (uint32_t)row * AROWB + seg * 16,
                     A + row * HH + k0 + seg * 8);
            }
            CPASYNC_MBAR_ARRIVE(mb + s * 16);                 // full[s] on completion
        }
    } else {
        // ================= compute warps (512 threads) =================
        const int m0w = (wid >> 1) * 16;
        const int n0w = (wid & 1) * 16;

        for (int t = 0; t < TT; t++) {
            const int par = t & 1;

            float acc[2][4];
#pragma unroll
            for (int nq = 0; nq < 2; nq++)
#pragma unroll
                for (int r = 0; r < 4; r++) acc[nq][r] = 0.0f;

            for (int ii = 0; ii < 16; ii++) {
                const int gi = t * 16 + ii, s = gi & 3;
                const int c = (c0 + ii) & 15;                 // rotated chunk id
                MBAR_WAIT(mb + s * 16, (gi >> 2) & 1);        // full[s]
                const uint32_t baseA = sb + OFFA + (uint32_t)s * ASLOT;
                const uint32_t aRow  = baseA + (uint32_t)(m0w + (lane & 15)) * AROWB
                                             + (uint32_t)((lane >> 4) * 8) * 2;
                const uint32_t bRow  = sb + OFFU
                                     + (uint32_t)(n0w + (lane >> 4) * 8 + (lane & 7)) * UROWB
                                     + (uint32_t)(c * 64 + ((lane >> 3) & 1) * 8) * 2;

                uint32_t ah[2][4], bh[2][4], bl[2][4];
                // prefetch kt=0
                ldmx4(ah[0], aRow);
                ldmx4(bh[0], bRow);
                ldmx4(bl[0], bRow + USIZE);
#pragma unroll
                for (int kt = 0; kt < 4; kt++) {
                    const int buf = kt & 1;
                    if (kt < 3) {                             // prefetch kt+1
                        ldmx4(ah[buf ^ 1], aRow + (uint32_t)((kt + 1) * 16) * 2);
                        ldmx4(bh[buf ^ 1], bRow + (uint32_t)((kt + 1) * 16) * 2);
                        ldmx4(bl[buf ^ 1], bRow + (uint32_t)((kt + 1) * 16) * 2 + USIZE);
                    } else if (ii < 15) {
                        MBARRIER_ARRIVE(mb + s * 16 + 8);     // empty[s]: frags in regs
                    }
#pragma unroll
                    for (int nq = 0; nq < 2; nq++) {
                        mma_f16(acc[nq], ah[buf], bh[buf] + nq * 2);  // A * Uhi
                        mma_f16(acc[nq], ah[buf], bl[buf] + nq * 2);  // A * Ulo
                    }
                }
            }

            asm volatile("bar.sync 1, 512;" ::: "memory");    // all MMA reads done

            // ---- stage z into ring slot 3 (16896 B <= 18432 B) ----
            float* z = (float*)(smem + OFFA + 3 * ASLOT);
#pragma unroll
            for (int nq = 0; nq < 2; nq++) {
                int r0 = m0w + (lane >> 2);
                int c0z = n0w + nq * 8 + (lane & 3) * 2;
                z[r0 * 33 + c0z]           = acc[nq][0];
                z[r0 * 33 + c0z + 1]       = acc[nq][1];
                z[(r0 + 8) * 33 + c0z]     = acc[nq][2];
                z[(r0 + 8) * 33 + c0z + 1] = acc[nq][3];
            }
            asm volatile("bar.sync 1, 512;" ::: "memory");

            // ---- fused gate epilogue (j-minor, coalesced float4 bias gather) ----
            const int jp = tid & 7;
            const int j  = bx * 8 + jp;
            __half* __restrict__ hf = g_hf16[par ^ 1];

#pragma unroll
            for (int mi = 0; mi < 2; mi++) {
                int m   = (tid >> 3) + mi * 64;
                int tok = g_tokT[t * BB + m];
                bool mk = (tok != 0);
                float4 ew4 = *(const float4*)(g_embW + (size_t)tok * FH + bx * 32 + jp * 4);
                float zi = z[m * 33 + 4 * jp + 0] + ew4.x;
                float zf = z[m * 33 + 4 * jp + 1] + ew4.y;
                float zg = z[m * 33 + 4 * jp + 2] + ew4.z;
                float zo = z[m * 33 + 4 * jp + 3] + ew4.w;
                float ig = sigm_fast(zi);
                float fg = sigm_fast(zf);
                float gg = tanh_fast(zg);
                float og = sigm_fast(zo);
                float cp = s_c[m * 8 + jp];
                float cn = fg * cp + ig * gg;
                float hn = og * tanh_fast(cn);
                float hp = s_h[m * 8 + jp];
                float ho = mk ? hn : hp;
                float co = mk ? cn : cp;
                s_c[m * 8 + jp] = co;
                s_h[m * 8 + jp] = ho;
                hf[m * HH + j] = __float2half(ho);
                g_states[((size_t)m * TT + t) * HH + j] = ho;
            }

            asm volatile("bar.sync 1, 512;" ::: "memory");    // epilogue stores done
            if (tid == 0) {
                __threadfence();                              // publish h before flagging
                atomicAdd(&g_chunk_cnt[bx >> 3], 1u);
            }
            MBARRIER_ARRIVE(mb + 3 * 16 + 8);                 // release slot 3 (z region)
        }
    }
}

// ======================= logits = states @ Wd + bd =======================
__global__ void __launch_bounds__(256) logits_kernel(const float* __restrict__ Wd,
                                                     const float* __restrict__ bd,
                                                     float* __restrict__ out) {
    __shared__ float Ss[32][33];
    __shared__ float Ws[32][128];

    const int tid = threadIdx.x;
    const int tx  = tid & 31;
    const int ty  = tid >> 5;
    const size_t row0 = (size_t)blockIdx.x * 32;

    float acc[4][4];
#pragma unroll
    for (int i = 0; i < 4; i++)
#pragma unroll
        for (int jn = 0; jn < 4; jn++) acc[i][jn] = 0.0f;

    for (int k0 = 0; k0 < HH; k0 += 32) {
#pragma unroll
        for (int r = 0; r < 4; r++) {
            int idx = tid + r * 256;
            int rr = idx >> 5, kk = idx & 31;
            Ss[rr][kk] = g_states[(row0 + rr) * HH + k0 + kk];
        }
#pragma unroll
        for (int r = 0; r < 16; r++) {
            int idx = tid + r * 256;
            int kk = idx >> 7, v = idx & 127;
            Ws[kk][v] = Wd[(k0 + kk) * VV + v];
        }
        __syncthreads();
#pragma unroll
        for (int kk = 0; kk < 32; kk++) {
            float4 b4 = *reinterpret_cast<const float4*>(&Ws[kk][tx * 4]);
            float a0 = Ss[ty * 4 + 0][kk];
            float a1 = Ss[ty * 4 + 1][kk];
            float a2 = Ss[ty * 4 + 2][kk];
            float a3 = Ss[ty * 4 + 3][kk];
            acc[0][0] = fmaf(a0, b4.x, acc[0][0]);
            acc[0][1] = fmaf(a0, b4.y, acc[0][1]);
            acc[0][2] = fmaf(a0, b4.z, acc[0][2]);
            acc[0][3] = fmaf(a0, b4.w, acc[0][3]);
            acc[1][0] = fmaf(a1, b4.x, acc[1][0]);
            acc[1][1] = fmaf(a1, b4.y, acc[1][1]);
            acc[1][2] = fmaf(a1, b4.z, acc[1][2]);
            acc[1][3] = fmaf(a1, b4.w, acc[1][3]);
            acc[2][0] = fmaf(a2, b4.x, acc[2][0]);
            acc[2][1] = fmaf(a2, b4.y, acc[2][1]);
            acc[2][2] = fmaf(a2, b4.z, acc[2][2]);
            acc[2][3] = fmaf(a2, b4.w, acc[2][3]);
            acc[3][0] = fmaf(a3, b4.x, acc[3][0]);
            acc[3][1] = fmaf(a3, b4.y, acc[3][1]);
            acc[3][2] = fmaf(a3, b4.z, acc[3][2]);
            acc[3][3] = fmaf(a3, b4.w, acc[3][3]);
        }
        __syncthreads();
    }

#pragma unroll
    for (int im = 0; im < 4; im++)
#pragma unroll
        for (int iv = 0; iv < 4; iv++) {
            int v = tx * 4 + iv;
            out[(row0 + ty * 4 + im) * VV + v] = acc[im][iv] + bd[v];
        }
}

// ======================= row softmax (V=128) =======================
__global__ void softmax_kernel(float* __restrict__ out) {
    __shared__ float red[4];
    const size_t row = blockIdx.x;
    const int v    = threadIdx.x;
    const int lane = v & 31;
    const int wid  = v >> 5;

    float x = out[row * VV + v];

    float mval = x;
#pragma unroll
    for (int o = 16; o > 0; o >>= 1)
        mval = fmaxf(mval, __shfl_xor_sync(0xFFFFFFFFu, mval, o));
    if (lane == 0) red[wid] = mval;
    __syncthreads();
    mval = fmaxf(fmaxf(red[0], red[1]), fmaxf(red[2], red[3]));
    __syncthreads();

    float e = expf(x - mval);
    float s = e;
#pragma unroll
    for (int o = 16; o > 0; o >>= 1)
        s += __shfl_xor_sync(0xFFFFFFFFu, s, o);
    if (lane == 0) red[wid] = s;
    __syncthreads();
    s = red[0] + red[1] + red[2] + red[3];

    out[row * VV + v] = e / s;
}

// ======================= launch =======================
extern "C" void kernel_launch(void* const* d_in, const int* in_sizes, int n_in,
                              void* d_out, int out_size) {
    const int*   tokens = (const int*)  d_in[0];
    const float* emb    = (const float*)d_in[1];
    const float* W      = (const float*)d_in[2];
    const float* U      = (const float*)d_in[3];
    const float* b      = (const float*)d_in[4];
    const float* Wd     = (const float*)d_in[5];
    const float* bd     = (const float*)d_in[6];
    float* out = (float*)d_out;

    cudaFuncSetAttribute(lstm_persistent, cudaFuncAttributeMaxDynamicSharedMemorySize, STEP_SMEM);

    zero_hc_kernel<<<512, 256>>>();
    tokT_kernel<<<TT, BB>>>(tokens);
    usplit_kernel<<<(FH * HH) / 256, 256>>>(U);
    embw_kernel<<<dim3(16, 128), 256>>>(emb, W, b);

    lstm_persistent<<<128, 640, STEP_SMEM>>>();

    logits_kernel<<<2048, 256>>>(Wd, bd, out);
    softmax_kernel<<<BB * TT, 128>>>(out);
}